// round 1
// baseline (speedup 1.0000x reference)
#include <cuda_runtime.h>

// Problem constants (fixed by reference setup_inputs)
#define BATCH    8
#define H        200
#define W        200
#define C        256
#define CROP     7
#define NROIS    512

// Derived
#define C4       (C / 4)                      // 64 float4 per pixel
#define NPOS     (BATCH * NROIS * CROP * CROP) // 200704 output positions
#define POS_PER_BLOCK 4                        // 256 threads / 64

__global__ __launch_bounds__(256)
void roi_crop_resize_kernel(const float4* __restrict__ img,   // [B*H*W, 64] float4
                            const float4* __restrict__ rois,  // [4096] float4 (y1,x1,y2,x2)
                            float4* __restrict__ out)         // [NPOS, 64] float4
{
    const int tid = threadIdx.x;
    const int pos = blockIdx.x * POS_PER_BLOCK + (tid >> 6); // output position 0..NPOS-1
    const int c4  = tid & 63;                                // float4 channel chunk

    // Decode position -> (roi, iy, ix)
    const int pix = pos % (CROP * CROP);
    const int r   = pos / (CROP * CROP);     // global roi 0..4095
    const int iy  = pix / CROP;
    const int ix  = pix % CROP;
    const int b   = r >> 9;                  // r / NROIS

    // Box (y1,x1,y2,x2) normalized
    const float4 box = __ldg(&rois[r]);
    const float by1 = box.x, bx1 = box.y, by2 = box.z, bx2 = box.w;

    // Match reference math exactly:
    // ys = y1*(H-1) + i * ((y2-y1)*(H-1)/(crop-1))
    const float ys = by1 * (float)(H - 1)
                   + (float)iy * ((by2 - by1) * (float)(H - 1) / (float)(CROP - 1));
    const float xs = bx1 * (float)(W - 1)
                   + (float)ix * ((bx2 - bx1) * (float)(W - 1) / (float)(CROP - 1));

    const bool valid = (ys >= 0.0f) && (ys <= (float)(H - 1)) &&
                       (xs >= 0.0f) && (xs <= (float)(W - 1));

    const float y0f = floorf(ys);
    const float x0f = floorf(xs);
    const float fy  = ys - y0f;
    const float fx  = xs - x0f;

    int y0 = (int)y0f;  y0 = min(max(y0, 0), H - 1);
    int x0 = (int)x0f;  x0 = min(max(x0, 0), W - 1);
    const int y1i = min(y0 + 1, H - 1);
    const int x1i = min(x0 + 1, W - 1);

    // Pixel -> float4 index: ((b*H + y)*W + x) * 64 + c4   (max ~20.5M, fits int)
    const int row0 = (b * H + y0)  * W;
    const int row1 = (b * H + y1i) * W;
    const int i00 = (row0 + x0)  * C4 + c4;
    const int i01 = (row0 + x1i) * C4 + c4;
    const int i10 = (row1 + x0)  * C4 + c4;
    const int i11 = (row1 + x1i) * C4 + c4;

    const float4 v00 = __ldg(&img[i00]);
    const float4 v01 = __ldg(&img[i01]);
    const float4 v10 = __ldg(&img[i10]);
    const float4 v11 = __ldg(&img[i11]);

    float4 res;
    {
        // top = v00 + (v01-v00)*fx ; bot = v10 + (v11-v10)*fx ; out = top + (bot-top)*fy
        float tx, bx2c;
        tx   = v00.x + (v01.x - v00.x) * fx;
        bx2c = v10.x + (v11.x - v10.x) * fx;
        res.x = tx + (bx2c - tx) * fy;

        tx   = v00.y + (v01.y - v00.y) * fx;
        bx2c = v10.y + (v11.y - v10.y) * fx;
        res.y = tx + (bx2c - tx) * fy;

        tx   = v00.z + (v01.z - v00.z) * fx;
        bx2c = v10.z + (v11.z - v10.z) * fx;
        res.z = tx + (bx2c - tx) * fy;

        tx   = v00.w + (v01.w - v00.w) * fx;
        bx2c = v10.w + (v11.w - v10.w) * fx;
        res.w = tx + (bx2c - tx) * fy;
    }

    if (!valid) { res.x = 0.0f; res.y = 0.0f; res.z = 0.0f; res.w = 0.0f; }

    out[pos * C4 + c4] = res;
}

extern "C" void kernel_launch(void* const* d_in, const int* in_sizes, int n_in,
                              void* d_out, int out_size)
{
    const float4* img  = (const float4*)d_in[0];   // [8,200,200,256] fp32
    const float4* rois = (const float4*)d_in[1];   // [8,512,4] fp32
    float4* out        = (float4*)d_out;           // [8,512,7,7,256] fp32

    const int blocks = NPOS / POS_PER_BLOCK;       // 200704 / 4 = 50176
    roi_crop_resize_kernel<<<blocks, 256>>>(img, rois, out);
}

// round 2
// speedup vs baseline: 1.0169x; 1.0169x over previous
#include <cuda_runtime.h>

// Problem constants (fixed by reference setup_inputs)
#define BATCH    8
#define H        200
#define W        200
#define C        256
#define CROP     7
#define NROIS    512

#define C4       (C / 4)                       // 64 float4 per pixel
#define NPOS     (BATCH * NROIS * CROP * CROP) // 200704 output positions
#define POS_PER_BLOCK 8                        // 256 threads / 32

__device__ __forceinline__ float4 lerp2d(const float4 v00, const float4 v01,
                                         const float4 v10, const float4 v11,
                                         const float fx, const float fy)
{
    float4 r;
    float t, b;
    t = v00.x + (v01.x - v00.x) * fx;  b = v10.x + (v11.x - v10.x) * fx;  r.x = t + (b - t) * fy;
    t = v00.y + (v01.y - v00.y) * fx;  b = v10.y + (v11.y - v10.y) * fx;  r.y = t + (b - t) * fy;
    t = v00.z + (v01.z - v00.z) * fx;  b = v10.z + (v11.z - v10.z) * fx;  r.z = t + (b - t) * fy;
    t = v00.w + (v01.w - v00.w) * fx;  b = v10.w + (v11.w - v10.w) * fx;  r.w = t + (b - t) * fy;
    return r;
}

__device__ __forceinline__ void stcs4(float4* p, const float4 v)
{
    // streaming store: evict-first in L2 so write-once output doesn't evict image lines
    asm volatile("st.global.cs.v4.f32 [%0], {%1, %2, %3, %4};"
                 :: "l"(p), "f"(v.x), "f"(v.y), "f"(v.z), "f"(v.w) : "memory");
}

__global__ __launch_bounds__(256)
void roi_crop_resize_kernel(const float4* __restrict__ img,   // [B*H*W, 64] float4
                            const float4* __restrict__ rois,  // [4096] float4 (y1,x1,y2,x2)
                            float4* __restrict__ out)         // [NPOS, 64] float4
{
    const int tid  = threadIdx.x;
    const int lane = tid & 31;
    const int pos  = blockIdx.x * POS_PER_BLOCK + (tid >> 5);

    // Decode position -> (roi, iy, ix). All warp-uniform.
    const int pix = pos % (CROP * CROP);
    const int r   = pos / (CROP * CROP);
    const int iy  = pix / CROP;
    const int ix  = pix % CROP;
    const int b   = r >> 9;

    const float4 box = __ldg(&rois[r]);
    const float by1 = box.x, bx1 = box.y, by2 = box.z, bx2 = box.w;

    // Match reference math exactly:
    // ys = y1*(H-1) + i * ((y2-y1)*(H-1)/(crop-1))
    const float ys = by1 * (float)(H - 1)
                   + (float)iy * ((by2 - by1) * (float)(H - 1) / (float)(CROP - 1));
    const float xs = bx1 * (float)(W - 1)
                   + (float)ix * ((bx2 - bx1) * (float)(W - 1) / (float)(CROP - 1));

    const bool valid = (ys >= 0.0f) && (ys <= (float)(H - 1)) &&
                       (xs >= 0.0f) && (xs <= (float)(W - 1));

    const float y0f = floorf(ys);
    const float x0f = floorf(xs);
    const float fy  = ys - y0f;
    const float fx  = xs - x0f;

    int y0 = (int)y0f;  y0 = min(max(y0, 0), H - 1);
    int x0 = (int)x0f;  x0 = min(max(x0, 0), W - 1);
    const int y1i = min(y0 + 1, H - 1);
    const int x1i = min(x0 + 1, W - 1);

    const int row0 = (b * H + y0)  * W;
    const int row1 = (b * H + y1i) * W;
    const int p00 = (row0 + x0)  * C4;
    const int p01 = (row0 + x1i) * C4;
    const int p10 = (row1 + x0)  * C4;
    const int p11 = (row1 + x1i) * C4;

    const int ca = lane;        // channel chunk A: float4 0..31
    const int cb = lane + 32;   // channel chunk B: float4 32..63

    // 8 independent 128-bit loads in flight (MLP=8)
    const float4 a00 = __ldg(&img[p00 + ca]);
    const float4 a01 = __ldg(&img[p01 + ca]);
    const float4 a10 = __ldg(&img[p10 + ca]);
    const float4 a11 = __ldg(&img[p11 + ca]);
    const float4 b00 = __ldg(&img[p00 + cb]);
    const float4 b01 = __ldg(&img[p01 + cb]);
    const float4 b10 = __ldg(&img[p10 + cb]);
    const float4 b11 = __ldg(&img[p11 + cb]);

    float4 resA = lerp2d(a00, a01, a10, a11, fx, fy);
    float4 resB = lerp2d(b00, b01, b10, b11, fx, fy);

    if (!valid) {
        resA.x = resA.y = resA.z = resA.w = 0.0f;
        resB.x = resB.y = resB.z = resB.w = 0.0f;
    }

    float4* obase = (float4*)out + (size_t)pos * C4;
    stcs4(obase + ca, resA);
    stcs4(obase + cb, resB);
}

extern "C" void kernel_launch(void* const* d_in, const int* in_sizes, int n_in,
                              void* d_out, int out_size)
{
    const float4* img  = (const float4*)d_in[0];   // [8,200,200,256] fp32
    const float4* rois = (const float4*)d_in[1];   // [8,512,4] fp32
    float4* out        = (float4*)d_out;           // [8,512,7,7,256] fp32

    const int blocks = NPOS / POS_PER_BLOCK;       // 200704 / 8 = 25088
    roi_crop_resize_kernel<<<blocks, 256>>>(img, rois, out);
}